// round 7
// baseline (speedup 1.0000x reference)
#include <cuda_runtime.h>
#include <cuda_bf16.h>
#include <math.h>
#include <stdint.h>

#define BATCH 4
#define CCH   512
#define HW    4096

typedef __nv_bfloat16 bf16;

// ---------------- scratch (static __device__ — no allocation allowed) -------
__device__ float g_mean_cc[BATCH*CCH];
__device__ float g_inv_cc [BATCH*CCH];
__device__ float g_mean_ss[BATCH*CCH];
__device__ float g_inv_ss [BATCH*CCH];
__device__ float g_b1p[BATCH*CCH];
__device__ float g_b2p[BATCH*CCH];

__device__ bf16 g_W1h[BATCH*CCH*CCH], g_W1l[BATCH*CCH*CCH];
__device__ bf16 g_W2h[BATCH*CCH*CCH], g_W2l[BATCH*CCH*CCH];
__device__ bf16 g_w3h[CCH*CCH],       g_w3l[CCH*CCH];
__device__ bf16 g_wrh[CCH*CCH],       g_wrl[CCH*CCH];

__device__ bf16 g_Xch[(size_t)BATCH*HW*CCH], g_Xcl[(size_t)BATCH*HW*CCH]; // x_fcc^T
__device__ bf16 g_Xsh[(size_t)BATCH*HW*CCH], g_Xsl[(size_t)BATCH*HW*CCH]; // x_fss^T
__device__ bf16 g_Qh [(size_t)BATCH*HW*CCH], g_Ql [(size_t)BATCH*HW*CCH];
__device__ bf16 g_Kh [(size_t)BATCH*HW*CCH], g_Kl [(size_t)BATCH*HW*CCH];
__device__ bf16 g_Vth[(size_t)BATCH*CCH*HW], g_Vtl[(size_t)BATCH*CCH*HW];
__device__ bf16 g_Oh [(size_t)BATCH*HW*CCH], g_Ol [(size_t)BATCH*HW*CCH];
__device__ bf16 g_Ah [(size_t)BATCH*HW*HW],  g_Al [(size_t)BATCH*HW*HW];
__device__ float g_S [(size_t)BATCH*HW*HW];   // fp32 scores (256 MB)

// ---------------- small helpers ----------------------------------------------
__device__ __forceinline__ float warpSum(float v) {
    #pragma unroll
    for (int o = 16; o > 0; o >>= 1) v += __shfl_down_sync(0xffffffffu, v, o);
    return v;
}
__device__ __forceinline__ float warpMax(float v) {
    #pragma unroll
    for (int o = 16; o > 0; o >>= 1) v = fmaxf(v, __shfl_down_sync(0xffffffffu, v, o));
    return v;
}
__device__ __forceinline__ uint32_t smem_u32(const void* p) {
    uint32_t a;
    asm("{ .reg .u64 t; cvta.to.shared.u64 t, %1; cvt.u32.u64 %0, t; }" : "=r"(a) : "l"(p));
    return a;
}
__device__ __forceinline__ void split_bf16(float v, bf16 &hi, bf16 &lo) {
    hi = __float2bfloat16_rn(v);
    lo = __float2bfloat16_rn(v - __bfloat162float(hi));
}

// ---------------- HMMA primitives (baseline PTX, no 'a' features) ------------
__device__ __forceinline__ void ldsm4(uint32_t* r, uint32_t addr) {
    asm volatile("ldmatrix.sync.aligned.m8n8.x4.shared.b16 {%0,%1,%2,%3}, [%4];"
        : "=r"(r[0]), "=r"(r[1]), "=r"(r[2]), "=r"(r[3]) : "r"(addr));
}
__device__ __forceinline__ void mma_bf16(float* c, const uint32_t* a,
                                         uint32_t b0, uint32_t b1) {
    asm volatile(
        "mma.sync.aligned.m16n8k16.row.col.f32.bf16.bf16.f32 "
        "{%0,%1,%2,%3}, {%4,%5,%6,%7}, {%8,%9}, {%0,%1,%2,%3};"
        : "+f"(c[0]), "+f"(c[1]), "+f"(c[2]), "+f"(c[3])
        : "r"(a[0]), "r"(a[1]), "r"(a[2]), "r"(a[3]), "r"(b0), "r"(b1));
}
__device__ __forceinline__ void cp16(uint32_t saddr, const void* g) {
    asm volatile("cp.async.cg.shared.global [%0], [%1], 16;"
                 :: "r"(saddr), "l"(g) : "memory");
}
#define CP_COMMIT() asm volatile("cp.async.commit_group;" ::: "memory")
#define CP_WAIT2()  asm volatile("cp.async.wait_group 2;" ::: "memory")
#define CP_WAIT0()  asm volatile("cp.async.wait_group 0;" ::: "memory")

// ---------------- instance-norm stats ---------------------------------------
__global__ __launch_bounds__(256) void stats_kernel(
    const float* __restrict__ x, float* __restrict__ mean, float* __restrict__ inv)
{
    int row = blockIdx.x;
    const float* p = x + (size_t)row * HW;
    float s = 0.f, sq = 0.f;
    for (int i = threadIdx.x; i < HW; i += 256) { float v = p[i]; s += v; sq += v * v; }
    s = warpSum(s); sq = warpSum(sq);
    __shared__ float ss[8], ssq[8];
    int w = threadIdx.x >> 5, lane = threadIdx.x & 31;
    if (lane == 0) { ss[w] = s; ssq[w] = sq; }
    __syncthreads();
    if (threadIdx.x == 0) {
        float S = 0.f, SQ = 0.f;
        #pragma unroll
        for (int i = 0; i < 8; i++) { S += ss[i]; SQ += ssq[i]; }
        float m = S / (float)HW;
        float var = (SQ - (float)HW * m * m) / (float)(HW - 1);
        mean[row] = m;
        inv[row]  = rsqrtf(var + 1e-5f);
    }
}

// ---------------- fold inst-norm into conv weights, emit bf16 hi/lo ----------
__global__ __launch_bounds__(128) void fold_kernel(
    const float* __restrict__ W, const float* __restrict__ bias,
    const float* __restrict__ mean, const float* __restrict__ inv,
    bf16* __restrict__ Wh, bf16* __restrict__ Wl, float* __restrict__ bp)
{
    int o = blockIdx.x, b = blockIdx.y;
    const float* mr = mean + b * CCH;
    const float* ir = inv  + b * CCH;
    float part = 0.f;
    for (int c = threadIdx.x; c < CCH; c += 128) {
        float w  = W[o * CCH + c];
        float iv = ir[c];
        float wp = w * iv;
        bf16 hi, lo; split_bf16(wp, hi, lo);
        size_t idx = ((size_t)b * CCH + o) * CCH + c;
        Wh[idx] = hi; Wl[idx] = lo;
        part += w * mr[c] * iv;
    }
    part = warpSum(part);
    __shared__ float sp[4];
    int w = threadIdx.x >> 5, lane = threadIdx.x & 31;
    if (lane == 0) sp[w] = part;
    __syncthreads();
    if (threadIdx.x == 0) bp[b * CCH + o] = bias[o] - (sp[0] + sp[1] + sp[2] + sp[3]);
}

// ---------------- plain weight split -----------------------------------------
__global__ __launch_bounds__(256) void split_kernel(
    const float* __restrict__ W, bf16* __restrict__ Wh, bf16* __restrict__ Wl, int n)
{
    int i = blockIdx.x * 256 + threadIdx.x;
    if (i < n) { bf16 hi, lo; split_bf16(W[i], hi, lo); Wh[i] = hi; Wl[i] = lo; }
}

// ---------------- transpose + split: X[C][HW] -> Xt hi/lo [HW][C] ------------
__global__ __launch_bounds__(256) void transpose_split(
    const float* __restrict__ X, bf16* __restrict__ Th, bf16* __restrict__ Tl)
{
    int b = blockIdx.z;
    X  += (size_t)b * CCH * HW;
    Th += (size_t)b * HW * CCH;
    Tl += (size_t)b * HW * CCH;
    __shared__ float t[32][33];
    int p0 = blockIdx.x * 32, c0 = blockIdx.y * 32;
    int tx = threadIdx.x & 31, ty = threadIdx.x >> 5;   // 32 x 8
    #pragma unroll
    for (int j = 0; j < 4; j++) {
        int cl = ty * 4 + j;
        t[cl][tx] = X[(size_t)(c0 + cl) * HW + p0 + tx];
    }
    __syncthreads();
    #pragma unroll
    for (int j = 0; j < 4; j++) {
        int pl = ty * 4 + j;
        float v = t[tx][pl];
        bf16 hi, lo; split_bf16(v, hi, lo);
        size_t idx = (size_t)(p0 + pl) * CCH + c0 + tx;
        Th[idx] = hi; Tl[idx] = lo;
    }
}

// ---------------- HMMA NT GEMM: D = Ah Bh^T + Ah Bl^T + Al Bh^T --------------
// A: [M][K] bf16 k-contig, B: [N][K] bf16 k-contig.
// Block 128x128, 8 warps (2x4), warp tile 64x32, k-tile 32.
// 4-stage cp.async ring, wait_group 2, one barrier per k-tile.
// EPI: 0 fp32 C; 1 bias[n] + bf16 hi/lo; 2 bias[m] + bf16 hi/lo;
//      3 bf16 hi/lo; 4 bias[m] + resid + fp32 C
#define KTILE 32
#define SROW  80                 // padded row stride bytes (32 bf16 + 16B pad)
#define ABYTES (128 * SROW)      // 10240 per operand tile
#define BUFBYTES (4 * ABYTES)    // Ah, Al, Bh, Bl -> 40960
#define NSTAGE 4
#define SMEMTOT (NSTAGE * BUFBYTES)   // 163840

template<int EPI>
__global__ __launch_bounds__(256) void hgemm(
    const bf16* __restrict__ Ah, const bf16* __restrict__ Al,
    const bf16* __restrict__ Bh, const bf16* __restrict__ Bl,
    int Kpass, size_t sA, size_t sB,
    float* __restrict__ C, size_t sC,
    bf16* __restrict__ Chi, bf16* __restrict__ Clo, size_t sCh,
    int ldc,
    const float* __restrict__ bias, size_t sBias,
    const float* __restrict__ resid, size_t sResid)
{
    extern __shared__ __align__(16) char smem[];
    const int tid  = threadIdx.x;
    const int wid  = tid >> 5, lane = tid & 31;
    const int wm   = wid >> 2, wn = wid & 3;      // 2 x 4 warp grid
    const int bz   = blockIdx.z;
    const int m0   = blockIdx.y * 128;
    const int n0   = blockIdx.x * 128;

    const char* gAh = (const char*)(Ah + bz * sA);
    const char* gAl = (const char*)(Al + bz * sA);
    const char* gBh = (const char*)(Bh + bz * sB);
    const char* gBl = (const char*)(Bl + bz * sB);
    const size_t rowB = (size_t)Kpass * 2;

    const uint32_t sb = smem_u32(smem);

    // per-thread gmem/smem chunk mapping: 512 chunks of 16B per operand tile
    const int ch0 = tid, ch1 = tid + 256;
    const int r0c = ch0 >> 2, c0c = (ch0 & 3) * 16;
    const int r1c = ch1 >> 2, c1c = (ch1 & 3) * 16;
    const uint32_t so0 = (uint32_t)(r0c * SROW + c0c);
    const uint32_t so1 = (uint32_t)(r1c * SROW + c1c);

    auto issue = [&](int t, int buf) {
        const size_t kb = (size_t)t * (KTILE * 2);      // byte offset along K
        const uint32_t s = sb + buf * BUFBYTES;
        const size_t ga0 = (size_t)(m0 + r0c) * rowB + kb + c0c;
        const size_t ga1 = (size_t)(m0 + r1c) * rowB + kb + c1c;
        const size_t gb0 = (size_t)(n0 + r0c) * rowB + kb + c0c;
        const size_t gb1 = (size_t)(n0 + r1c) * rowB + kb + c1c;
        cp16(s              + so0, gAh + ga0);
        cp16(s              + so1, gAh + ga1);
        cp16(s +   ABYTES   + so0, gAl + ga0);
        cp16(s +   ABYTES   + so1, gAl + ga1);
        cp16(s + 2*ABYTES   + so0, gBh + gb0);
        cp16(s + 2*ABYTES   + so1, gBh + gb1);
        cp16(s + 3*ABYTES   + so0, gBl + gb0);
        cp16(s + 3*ABYTES   + so1, gBl + gb1);
        CP_COMMIT();
    };

    float acc[4][4][4];
    #pragma unroll
    for (int i = 0; i < 4; i++)
        #pragma unroll
        for (int j = 0; j < 4; j++)
            #pragma unroll
            for (int q = 0; q < 4; q++) acc[i][j][q] = 0.f;

    const int nt = Kpass / KTILE;
    const int lr = lane & 15, lc = (lane >> 4) * 16;

    // prologue: fill 3 stages
    issue(0, 0); issue(1, 1); issue(2, 2);

    for (int t = 0; t < nt; t++) {
        const int buf = t & (NSTAGE - 1);
        CP_WAIT2();                 // oldest (tile t) complete; <=2 still in flight
        __syncthreads();            // all warps past compute of t-1; smem visible
        if (t + 3 < nt) issue(t + 3, (t + 3) & (NSTAGE - 1));

        const uint32_t aH = sb + buf * BUFBYTES;
        const uint32_t aL = aH + ABYTES;
        const uint32_t bH = aH + 2 * ABYTES;
        const uint32_t bL = aH + 3 * ABYTES;

        #pragma unroll
        for (int ks = 0; ks < 2; ks++) {
            const int kof = ks * 32;
            uint32_t ah[4][4], al[4][4], bh[2][4], bl[2][4];
            #pragma unroll
            for (int mt = 0; mt < 4; mt++) {
                uint32_t off = (uint32_t)((wm * 64 + mt * 16 + lr) * SROW + kof + lc);
                ldsm4(ah[mt], aH + off);
                ldsm4(al[mt], aL + off);
            }
            #pragma unroll
            for (int p = 0; p < 2; p++) {
                uint32_t off = (uint32_t)((wn * 32 + p * 16 + lr) * SROW + kof + lc);
                ldsm4(bh[p], bH + off);
                ldsm4(bl[p], bL + off);
            }
            #pragma unroll
            for (int mt = 0; mt < 4; mt++) {
                #pragma unroll
                for (int ntl = 0; ntl < 4; ntl++) {
                    const int p = ntl >> 1, h = ntl & 1;
                    mma_bf16(acc[mt][ntl], ah[mt], bh[p][h], bh[p][h + 2]);
                    mma_bf16(acc[mt][ntl], ah[mt], bl[p][h], bl[p][h + 2]);
                    mma_bf16(acc[mt][ntl], al[mt], bh[p][h], bh[p][h + 2]);
                }
            }
        }
    }
    CP_WAIT0();

    // ---- epilogue ----
    const int n_base = n0 + wn * 32;
    const int m_base = m0 + wm * 64;
    #pragma unroll
    for (int ntl = 0; ntl < 4; ntl++) {
        const int n = n_base + ntl * 8 + 2 * (lane & 3);
        float bn0 = 0.f, bn1 = 0.f;
        if (EPI == 1) {
            bn0 = bias[bz * sBias + n];
            bn1 = bias[bz * sBias + n + 1];
        }
        #pragma unroll
        for (int mt = 0; mt < 4; mt++) {
            #pragma unroll
            for (int half = 0; half < 2; half++) {
                const int m = m_base + mt * 16 + (lane >> 2) + half * 8;
                float v0 = acc[mt][ntl][half * 2 + 0];
                float v1 = acc[mt][ntl][half * 2 + 1];
                if (EPI == 1) { v0 += bn0; v1 += bn1; }
                if (EPI == 2 || EPI == 4) {
                    float bm = bias[bz * sBias + m];
                    v0 += bm; v1 += bm;
                }
                if (EPI == 4) {
                    const float* rp = resid + bz * sResid + (size_t)m * ldc + n;
                    v0 += rp[0]; v1 += rp[1];
                }
                if (EPI == 0 || EPI == 4) {
                    float2 o = make_float2(v0, v1);
                    *(float2*)(C + bz * sC + (size_t)m * ldc + n) = o;
                } else {
                    bf16 h0, l0, h1, l1;
                    split_bf16(v0, h0, l0);
                    split_bf16(v1, h1, l1);
                    __nv_bfloat162 hp; hp.x = h0; hp.y = h1;
                    __nv_bfloat162 lp; lp.x = l0; lp.y = l1;
                    *(__nv_bfloat162*)(Chi + bz * sCh + (size_t)m * ldc + n) = hp;
                    *(__nv_bfloat162*)(Clo + bz * sCh + (size_t)m * ldc + n) = lp;
                }
            }
        }
    }
}

// ---------------- softmax: fp32 scores row -> bf16 hi/lo A -------------------
__global__ __launch_bounds__(256) void softmax_split(
    const float* __restrict__ S, bf16* __restrict__ Ah, bf16* __restrict__ Al)
{
    const float* p = S + (size_t)blockIdx.x * HW;
    bf16* ah = Ah + (size_t)blockIdx.x * HW;
    bf16* al = Al + (size_t)blockIdx.x * HW;
    int tid = threadIdx.x;
    float vals[16];
    float mx = -INFINITY;
    #pragma unroll
    for (int i = 0; i < 16; i++) { vals[i] = p[tid + i * 256]; mx = fmaxf(mx, vals[i]); }
    __shared__ float sh[8];
    int w = tid >> 5, lane = tid & 31;
    mx = warpMax(mx);
    if (lane == 0) sh[w] = mx;
    __syncthreads();
    if (w == 0) {
        float v = (lane < 8) ? sh[lane] : -INFINITY;
        v = warpMax(v);
        if (lane == 0) sh[0] = v;
    }
    __syncthreads();
    mx = sh[0];
    __syncthreads();
    float s = 0.f;
    #pragma unroll
    for (int i = 0; i < 16; i++) { vals[i] = expf(vals[i] - mx); s += vals[i]; }
    s = warpSum(s);
    if (lane == 0) sh[w] = s;
    __syncthreads();
    if (w == 0) {
        float v = (lane < 8) ? sh[lane] : 0.f;
        v = warpSum(v);
        if (lane == 0) sh[0] = v;
    }
    __syncthreads();
    float invs = 1.f / sh[0];
    #pragma unroll
    for (int i = 0; i < 16; i++) {
        float v = vals[i] * invs;
        bf16 hi, lo; split_bf16(v, hi, lo);
        ah[tid + i * 256] = hi;
        al[tid + i * 256] = lo;
    }
}

// ---------------- launch -----------------------------------------------------
extern "C" void kernel_launch(void* const* d_in, const int* in_sizes, int n_in,
                              void* d_out, int out_size)
{
    const float* x_fcc = (const float*)d_in[0];
    const float* x_fss = (const float*)d_in[1];
    const float* w1  = (const float*)d_in[2];
    const float* b1  = (const float*)d_in[3];
    const float* w2  = (const float*)d_in[4];
    const float* b2  = (const float*)d_in[5];
    const float* w3  = (const float*)d_in[6];
    const float* b3  = (const float*)d_in[7];
    const float* wrs = (const float*)d_in[8];
    const float* brs = (const float*)d_in[9];
    float* out = (float*)d_out;

    #define SYM(p, s) void* p##_; cudaGetSymbolAddress(&p##_, s); auto p = (decltype(&s[0]))p##_;
    SYM(pMcc, g_mean_cc) SYM(pIcc, g_inv_cc) SYM(pMss, g_mean_ss) SYM(pIss, g_inv_ss)
    SYM(pB1, g_b1p) SYM(pB2, g_b2p)
    SYM(pW1h, g_W1h) SYM(pW1l, g_W1l) SYM(pW2h, g_W2h) SYM(pW2l, g_W2l)
    SYM(pw3h, g_w3h) SYM(pw3l, g_w3l) SYM(pwrh, g_wrh) SYM(pwrl, g_wrl)
    SYM(pXch, g_Xch) SYM(pXcl, g_Xcl) SYM(pXsh, g_Xsh) SYM(pXsl, g_Xsl)
    SYM(pQh, g_Qh) SYM(pQl, g_Ql) SYM(pKh, g_Kh) SYM(pKl, g_Kl)
    SYM(pVth, g_Vth) SYM(pVtl, g_Vtl) SYM(pOh, g_Oh) SYM(pOl, g_Ol)
    SYM(pAh, g_Ah) SYM(pAl, g_Al) SYM(pS, g_S)
    #undef SYM

    cudaFuncSetAttribute(hgemm<0>, cudaFuncAttributeMaxDynamicSharedMemorySize, SMEMTOT);
    cudaFuncSetAttribute(hgemm<1>, cudaFuncAttributeMaxDynamicSharedMemorySize, SMEMTOT);
    cudaFuncSetAttribute(hgemm<2>, cudaFuncAttributeMaxDynamicSharedMemorySize, SMEMTOT);
    cudaFuncSetAttribute(hgemm<3>, cudaFuncAttributeMaxDynamicSharedMemorySize, SMEMTOT);
    cudaFuncSetAttribute(hgemm<4>, cudaFuncAttributeMaxDynamicSharedMemorySize, SMEMTOT);

    // 1) instance-norm stats
    stats_kernel<<<BATCH * CCH, 256>>>(x_fcc, pMcc, pIcc);
    stats_kernel<<<BATCH * CCH, 256>>>(x_fss, pMss, pIss);

    // 2) fold norm into W1/W2 (bf16 hi/lo) + bias; split w3, wrs
    fold_kernel<<<dim3(CCH, BATCH), 128>>>(w1, b1, pMcc, pIcc, pW1h, pW1l, pB1);
    fold_kernel<<<dim3(CCH, BATCH), 128>>>(w2, b2, pMss, pIss, pW2h, pW2l, pB2);
    split_kernel<<<CCH * CCH / 256, 256>>>(w3,  pw3h, pw3l, CCH * CCH);
    split_kernel<<<CCH * CCH / 256, 256>>>(wrs, pwrh, pwrl, CCH * CCH);

    // 3) transpose + split inputs: X[C][HW] -> Xt[HW][C] bf16 hi/lo
    transpose_split<<<dim3(HW / 32, CCH / 32, BATCH), 256>>>(x_fcc, pXch, pXcl);
    transpose_split<<<dim3(HW / 32, CCH / 32, BATCH), 256>>>(x_fss, pXsh, pXsl);

    const size_t sX = (size_t)HW * CCH;     // bf16 activation batch stride
    const size_t sW = (size_t)CCH * CCH;
    const size_t sS = (size_t)HW * HW;
    const size_t sV = (size_t)CCH * HW;

    // 4) Q = Xcc_t W1'^T + b1'[n]   (M=HW, N=C)
    hgemm<1><<<dim3(CCH/128, HW/128, BATCH), 256, SMEMTOT>>>(
        pXch, pXcl, pW1h, pW1l, CCH, sX, sW,
        nullptr, 0, pQh, pQl, sX, CCH, pB1, CCH, nullptr, 0);
    //    K = Xss_t W2'^T + b2'[n]
    hgemm<1><<<dim3(CCH/128, HW/128, BATCH), 256, SMEMTOT>>>(
        pXsh, pXsl, pW2h, pW2l, CCH, sX, sW,
        nullptr, 0, pKh, pKl, sX, CCH, pB2, CCH, nullptr, 0);
    //    Vt = w3 Xss_t^T + b3[m]   (M=C, N=HW) -> Vt[o][p]
    hgemm<2><<<dim3(HW/128, CCH/128, BATCH), 256, SMEMTOT>>>(
        pw3h, pw3l, pXsh, pXsl, CCH, 0, sX,
        nullptr, 0, pVth, pVtl, sV, HW, b3, 0, nullptr, 0);

    // 5) scores = Q K^T (fp32 out), M=N=HW
    hgemm<0><<<dim3(HW/128, HW/128, BATCH), 256, SMEMTOT>>>(
        pQh, pQl, pKh, pKl, CCH, sX, sX,
        pS, sS, nullptr, nullptr, 0, HW, nullptr, 0, nullptr, 0);

    // 6) softmax -> A bf16 hi/lo
    softmax_split<<<BATCH * HW, 256>>>(pS, pAh, pAl);

    // 7) O = A Vt^T (M=HW, N=C, K=HW) -> O[q][c] bf16 hi/lo
    hgemm<3><<<dim3(CCH/128, HW/128, BATCH), 256, SMEMTOT>>>(
        pAh, pAl, pVth, pVtl, HW, sS, sV,
        nullptr, 0, pOh, pOl, sX, CCH, nullptr, 0, nullptr, 0);

    // 8) out = Wrs O^T + brs[m] + x_fcc  (M=C, N=HW, fp32)
    hgemm<4><<<dim3(HW/128, CCH/128, BATCH), 256, SMEMTOT>>>(
        pwrh, pwrl, pOh, pOl, CCH, 0, sX,
        out, (size_t)CCH * HW, nullptr, nullptr, 0, HW, brs, 0, x_fcc, (size_t)CCH * HW);
}

// round 8
// speedup vs baseline: 1.3371x; 1.3371x over previous
#include <cuda_runtime.h>
#include <cuda_bf16.h>
#include <cuda_fp16.h>
#include <math.h>
#include <stdint.h>

#define BATCH 4
#define CCH   512
#define HW    4096

typedef __nv_bfloat16 bf16;
typedef __half fp16;

// ---------------- scratch (static __device__ — no allocation allowed) -------
__device__ float g_mean_cc[BATCH*CCH];
__device__ float g_inv_cc [BATCH*CCH];
__device__ float g_mean_ss[BATCH*CCH];
__device__ float g_inv_ss [BATCH*CCH];
__device__ float g_b1p[BATCH*CCH];
__device__ float g_b2p[BATCH*CCH];

__device__ bf16 g_W1h[BATCH*CCH*CCH], g_W1l[BATCH*CCH*CCH];
__device__ bf16 g_W2h[BATCH*CCH*CCH], g_W2l[BATCH*CCH*CCH];
__device__ bf16 g_w3h[CCH*CCH],       g_w3l[CCH*CCH];
__device__ fp16 g_wrh[CCH*CCH],       g_wrl[CCH*CCH];

__device__ bf16 g_Xch[(size_t)BATCH*HW*CCH], g_Xcl[(size_t)BATCH*HW*CCH]; // x_fcc^T
__device__ bf16 g_Xsh[(size_t)BATCH*HW*CCH], g_Xsl[(size_t)BATCH*HW*CCH]; // x_fss^T
__device__ bf16 g_Qh [(size_t)BATCH*HW*CCH], g_Ql [(size_t)BATCH*HW*CCH];
__device__ bf16 g_Kh [(size_t)BATCH*HW*CCH], g_Kl [(size_t)BATCH*HW*CCH];
__device__ fp16 g_Vfh[(size_t)BATCH*CCH*HW], g_Vfl[(size_t)BATCH*CCH*HW]; // V^T fp16 hi/lo
__device__ fp16 g_Of [(size_t)BATCH*HW*CCH];                              // O fp16
__device__ fp16 g_Af [(size_t)BATCH*HW*HW];                               // softmax(A) fp16
__device__ float g_S [(size_t)BATCH*HW*HW];                               // fp32 scores

// ---------------- small helpers ----------------------------------------------
__device__ __forceinline__ float warpSum(float v) {
    #pragma unroll
    for (int o = 16; o > 0; o >>= 1) v += __shfl_down_sync(0xffffffffu, v, o);
    return v;
}
__device__ __forceinline__ float warpMax(float v) {
    #pragma unroll
    for (int o = 16; o > 0; o >>= 1) v = fmaxf(v, __shfl_down_sync(0xffffffffu, v, o));
    return v;
}
__device__ __forceinline__ uint32_t smem_u32(const void* p) {
    uint32_t a;
    asm("{ .reg .u64 t; cvta.to.shared.u64 t, %1; cvt.u32.u64 %0, t; }" : "=r"(a) : "l"(p));
    return a;
}
__device__ __forceinline__ void split_bf16(float v, bf16 &hi, bf16 &lo) {
    hi = __float2bfloat16_rn(v);
    lo = __float2bfloat16_rn(v - __bfloat162float(hi));
}
__device__ __forceinline__ void split_fp16(float v, fp16 &hi, fp16 &lo) {
    hi = __float2half_rn(v);
    lo = __float2half_rn(v - __half2float(hi));
}

// ---------------- MMA primitives (baseline PTX, no 'a' features) -------------
__device__ __forceinline__ void ldsm4(uint32_t* r, uint32_t addr) {
    asm volatile("ldmatrix.sync.aligned.m8n8.x4.shared.b16 {%0,%1,%2,%3}, [%4];"
        : "=r"(r[0]), "=r"(r[1]), "=r"(r[2]), "=r"(r[3]) : "r"(addr));
}
__device__ __forceinline__ void mma_bf16(float* c, const uint32_t* a,
                                         uint32_t b0, uint32_t b1) {
    asm volatile(
        "mma.sync.aligned.m16n8k16.row.col.f32.bf16.bf16.f32 "
        "{%0,%1,%2,%3}, {%4,%5,%6,%7}, {%8,%9}, {%0,%1,%2,%3};"
        : "+f"(c[0]), "+f"(c[1]), "+f"(c[2]), "+f"(c[3])
        : "r"(a[0]), "r"(a[1]), "r"(a[2]), "r"(a[3]), "r"(b0), "r"(b1));
}
__device__ __forceinline__ void mma_fp16(float* c, const uint32_t* a,
                                         uint32_t b0, uint32_t b1) {
    asm volatile(
        "mma.sync.aligned.m16n8k16.row.col.f32.f16.f16.f32 "
        "{%0,%1,%2,%3}, {%4,%5,%6,%7}, {%8,%9}, {%0,%1,%2,%3};"
        : "+f"(c[0]), "+f"(c[1]), "+f"(c[2]), "+f"(c[3])
        : "r"(a[0]), "r"(a[1]), "r"(a[2]), "r"(a[3]), "r"(b0), "r"(b1));
}
__device__ __forceinline__ void cp16(uint32_t saddr, const void* g) {
    asm volatile("cp.async.cg.shared.global [%0], [%1], 16;"
                 :: "r"(saddr), "l"(g) : "memory");
}
#define CP_COMMIT() asm volatile("cp.async.commit_group;" ::: "memory")
#define CP_WAIT0()  asm volatile("cp.async.wait_group 0;" ::: "memory")

// ---------------- instance-norm stats ---------------------------------------
__global__ __launch_bounds__(256) void stats_kernel(
    const float* __restrict__ x, float* __restrict__ mean, float* __restrict__ inv)
{
    int row = blockIdx.x;
    const float* p = x + (size_t)row * HW;
    float s = 0.f, sq = 0.f;
    for (int i = threadIdx.x; i < HW; i += 256) { float v = p[i]; s += v; sq += v * v; }
    s = warpSum(s); sq = warpSum(sq);
    __shared__ float ss[8], ssq[8];
    int w = threadIdx.x >> 5, lane = threadIdx.x & 31;
    if (lane == 0) { ss[w] = s; ssq[w] = sq; }
    __syncthreads();
    if (threadIdx.x == 0) {
        float S = 0.f, SQ = 0.f;
        #pragma unroll
        for (int i = 0; i < 8; i++) { S += ss[i]; SQ += ssq[i]; }
        float m = S / (float)HW;
        float var = (SQ - (float)HW * m * m) / (float)(HW - 1);
        mean[row] = m;
        inv[row]  = rsqrtf(var + 1e-5f);
    }
}

// ---------------- fold inst-norm into conv weights, emit bf16 hi/lo ----------
__global__ __launch_bounds__(128) void fold_kernel(
    const float* __restrict__ W, const float* __restrict__ bias,
    const float* __restrict__ mean, const float* __restrict__ inv,
    bf16* __restrict__ Wh, bf16* __restrict__ Wl, float* __restrict__ bp)
{
    int o = blockIdx.x, b = blockIdx.y;
    const float* mr = mean + b * CCH;
    const float* ir = inv  + b * CCH;
    float part = 0.f;
    for (int c = threadIdx.x; c < CCH; c += 128) {
        float w  = W[o * CCH + c];
        float iv = ir[c];
        float wp = w * iv;
        bf16 hi, lo; split_bf16(wp, hi, lo);
        size_t idx = ((size_t)b * CCH + o) * CCH + c;
        Wh[idx] = hi; Wl[idx] = lo;
        part += w * mr[c] * iv;
    }
    part = warpSum(part);
    __shared__ float sp[4];
    int w = threadIdx.x >> 5, lane = threadIdx.x & 31;
    if (lane == 0) sp[w] = part;
    __syncthreads();
    if (threadIdx.x == 0) bp[b * CCH + o] = bias[o] - (sp[0] + sp[1] + sp[2] + sp[3]);
}

// ---------------- weight splits ----------------------------------------------
__global__ __launch_bounds__(256) void split_kernel_bf(
    const float* __restrict__ W, bf16* __restrict__ Wh, bf16* __restrict__ Wl, int n)
{
    int i = blockIdx.x * 256 + threadIdx.x;
    if (i < n) { bf16 hi, lo; split_bf16(W[i], hi, lo); Wh[i] = hi; Wl[i] = lo; }
}
__global__ __launch_bounds__(256) void split_kernel_fp(
    const float* __restrict__ W, fp16* __restrict__ Wh, fp16* __restrict__ Wl, int n)
{
    int i = blockIdx.x * 256 + threadIdx.x;
    if (i < n) { fp16 hi, lo; split_fp16(W[i], hi, lo); Wh[i] = hi; Wl[i] = lo; }
}

// ---------------- transpose + split: X[C][HW] -> Xt hi/lo [HW][C] ------------
__global__ __launch_bounds__(256) void transpose_split(
    const float* __restrict__ X, bf16* __restrict__ Th, bf16* __restrict__ Tl)
{
    int b = blockIdx.z;
    X  += (size_t)b * CCH * HW;
    Th += (size_t)b * HW * CCH;
    Tl += (size_t)b * HW * CCH;
    __shared__ float t[32][33];
    int p0 = blockIdx.x * 32, c0 = blockIdx.y * 32;
    int tx = threadIdx.x & 31, ty = threadIdx.x >> 5;   // 32 x 8
    #pragma unroll
    for (int j = 0; j < 4; j++) {
        int cl = ty * 4 + j;
        t[cl][tx] = X[(size_t)(c0 + cl) * HW + p0 + tx];
    }
    __syncthreads();
    #pragma unroll
    for (int j = 0; j < 4; j++) {
        int pl = ty * 4 + j;
        float v = t[tx][pl];
        bf16 hi, lo; split_bf16(v, hi, lo);
        size_t idx = (size_t)(p0 + pl) * CCH + c0 + tx;
        Th[idx] = hi; Tl[idx] = lo;
    }
}

// ============= bf16 3-term NT GEMM (R6 config: 2-stage, 80KB) ================
// EPI: 0 fp32 C; 1 bias[n] + bf16 hi/lo; 5 bias[m] + fp16 hi/lo
#define KTILE 32
#define SROW  80
#define ABYTES (128 * SROW)          // 10240
#define BUFB4 (4 * ABYTES)           // 40960 (Ah, Al, Bh, Bl)
#define SMEM4 (2 * BUFB4)            // 81920
#define BUFB3 (3 * ABYTES)           // 30720
#define SMEM3 (2 * BUFB3)            // 61440

template<int EPI>
__global__ __launch_bounds__(256) void hgemm(
    const bf16* __restrict__ Ah, const bf16* __restrict__ Al,
    const bf16* __restrict__ Bh, const bf16* __restrict__ Bl,
    int Kpass, size_t sA, size_t sB,
    float* __restrict__ C, size_t sC,
    void* __restrict__ Chi, void* __restrict__ Clo, size_t sCh,
    int ldc,
    const float* __restrict__ bias, size_t sBias)
{
    extern __shared__ __align__(16) char smem[];
    const int tid  = threadIdx.x;
    const int wid  = tid >> 5, lane = tid & 31;
    const int wm   = wid >> 2, wn = wid & 3;
    const int bz   = blockIdx.z;
    const int m0   = blockIdx.y * 128;
    const int n0   = blockIdx.x * 128;

    const char* gAh = (const char*)(Ah + bz * sA);
    const char* gAl = (const char*)(Al + bz * sA);
    const char* gBh = (const char*)(Bh + bz * sB);
    const char* gBl = (const char*)(Bl + bz * sB);
    const size_t rowB = (size_t)Kpass * 2;

    const uint32_t sb = smem_u32(smem);
    const int ch0 = tid, ch1 = tid + 256;
    const int r0c = ch0 >> 2, c0c = (ch0 & 3) * 16;
    const int r1c = ch1 >> 2, c1c = (ch1 & 3) * 16;
    const uint32_t so0 = (uint32_t)(r0c * SROW + c0c);
    const uint32_t so1 = (uint32_t)(r1c * SROW + c1c);

    auto issue = [&](int t, int buf) {
        const size_t kb = (size_t)t * (KTILE * 2);
        const uint32_t s = sb + buf * BUFB4;
        const size_t ga0 = (size_t)(m0 + r0c) * rowB + kb + c0c;
        const size_t ga1 = (size_t)(m0 + r1c) * rowB + kb + c1c;
        const size_t gb0 = (size_t)(n0 + r0c) * rowB + kb + c0c;
        const size_t gb1 = (size_t)(n0 + r1c) * rowB + kb + c1c;
        cp16(s            + so0, gAh + ga0);
        cp16(s            + so1, gAh + ga1);
        cp16(s +   ABYTES + so0, gAl + ga0);
        cp16(s +   ABYTES + so1, gAl + ga1);
        cp16(s + 2*ABYTES + so0, gBh + gb0);
        cp16(s + 2*ABYTES + so1, gBh + gb1);
        cp16(s + 3*ABYTES + so0, gBl + gb0);
        cp16(s + 3*ABYTES + so1, gBl + gb1);
        CP_COMMIT();
    };

    float acc[4][4][4];
    #pragma unroll
    for (int i = 0; i < 4; i++)
        #pragma unroll
        for (int j = 0; j < 4; j++)
            #pragma unroll
            for (int q = 0; q < 4; q++) acc[i][j][q] = 0.f;

    const int nt = Kpass / KTILE;
    const int lr = lane & 15, lc = (lane >> 4) * 16;

    issue(0, 0);
    for (int t = 0; t < nt; t++) {
        const int buf = t & 1;
        CP_WAIT0();
        __syncthreads();
        if (t + 1 < nt) issue(t + 1, buf ^ 1);

        const uint32_t aH = sb + buf * BUFB4;
        const uint32_t aL = aH + ABYTES;
        const uint32_t bH = aH + 2 * ABYTES;
        const uint32_t bL = aH + 3 * ABYTES;

        #pragma unroll
        for (int ks = 0; ks < 2; ks++) {
            const int kof = ks * 32;
            uint32_t ah[4][4], al[4][4], bh[2][4], bl[2][4];
            #pragma unroll
            for (int mt = 0; mt < 4; mt++) {
                uint32_t off = (uint32_t)((wm * 64 + mt * 16 + lr) * SROW + kof + lc);
                ldsm4(ah[mt], aH + off);
                ldsm4(al[mt], aL + off);
            }
            #pragma unroll
            for (int p = 0; p < 2; p++) {
                uint32_t off = (uint32_t)((wn * 32 + p * 16 + lr) * SROW + kof + lc);
                ldsm4(bh[p], bH + off);
                ldsm4(bl[p], bL + off);
            }
            #pragma unroll
            for (int mt = 0; mt < 4; mt++) {
                #pragma unroll
                for (int ntl = 0; ntl < 4; ntl++) {
                    const int p = ntl >> 1, h = ntl & 1;
                    mma_bf16(acc[mt][ntl], ah[mt], bh[p][h], bh[p][h + 2]);
                    mma_bf16(acc[mt][ntl], ah[mt], bl[p][h], bl[p][h + 2]);
                    mma_bf16(acc[mt][ntl], al[mt], bh[p][h], bh[p][h + 2]);
                }
            }
        }
        __syncthreads();
    }

    // ---- epilogue ----
    const int n_base = n0 + wn * 32;
    const int m_base = m0 + wm * 64;
    #pragma unroll
    for (int ntl = 0; ntl < 4; ntl++) {
        const int n = n_base + ntl * 8 + 2 * (lane & 3);
        float bn0 = 0.f, bn1 = 0.f;
        if (EPI == 1) {
            bn0 = bias[bz * sBias + n];
            bn1 = bias[bz * sBias + n + 1];
        }
        #pragma unroll
        for (int mt = 0; mt < 4; mt++) {
            #pragma unroll
            for (int half = 0; half < 2; half++) {
                const int m = m_base + mt * 16 + (lane >> 2) + half * 8;
                float v0 = acc[mt][ntl][half * 2 + 0];
                float v1 = acc[mt][ntl][half * 2 + 1];
                if (EPI == 1) { v0 += bn0; v1 += bn1; }
                if (EPI == 5) {
                    float bm = bias[bz * sBias + m];
                    v0 += bm; v1 += bm;
                }
                if (EPI == 0) {
                    *(float2*)(C + bz * sC + (size_t)m * ldc + n) = make_float2(v0, v1);
                } else if (EPI == 1) {
                    bf16 h0, l0, h1, l1;
                    split_bf16(v0, h0, l0); split_bf16(v1, h1, l1);
                    __nv_bfloat162 hp; hp.x = h0; hp.y = h1;
                    __nv_bfloat162 lp; lp.x = l0; lp.y = l1;
                    *(__nv_bfloat162*)((bf16*)Chi + bz * sCh + (size_t)m * ldc + n) = hp;
                    *(__nv_bfloat162*)((bf16*)Clo + bz * sCh + (size_t)m * ldc + n) = lp;
                } else { // EPI == 5
                    fp16 h0, l0, h1, l1;
                    split_fp16(v0, h0, l0); split_fp16(v1, h1, l1);
                    __half2 hp; hp.x = h0; hp.y = h1;
                    __half2 lp; lp.x = l0; lp.y = l1;
                    *(__half2*)((fp16*)Chi + bz * sCh + (size_t)m * ldc + n) = hp;
                    *(__half2*)((fp16*)Clo + bz * sCh + (size_t)m * ldc + n) = lp;
                }
            }
        }
    }
}

// ============= fp16 2-term NT GEMM ==========================================
// MODE 0: A single fp16, B fp16 hi/lo (terms A·Bh + A·Bl)
// MODE 1: A fp16 hi/lo, B single fp16 (terms Ah·B + Al·B)
// EPI: 6 fp16 single out; 4 bias[m] + resid + fp32 C
template<int EPI, int MODE>
__global__ __launch_bounds__(256) void hgemm16(
    const fp16* __restrict__ A0, const fp16* __restrict__ A1,
    const fp16* __restrict__ B0, const fp16* __restrict__ B1,
    int Kpass, size_t sA, size_t sB,
    float* __restrict__ C, size_t sC,
    fp16* __restrict__ Cf, size_t sCf,
    int ldc,
    const float* __restrict__ bias, size_t sBias,
    const float* __restrict__ resid, size_t sResid)
{
    extern __shared__ __align__(16) char smem[];
    const int tid  = threadIdx.x;
    const int wid  = tid >> 5, lane = tid & 31;
    const int wm   = wid >> 2, wn = wid & 3;
    const int bz   = blockIdx.z;
    const int m0   = blockIdx.y * 128;
    const int n0   = blockIdx.x * 128;

    const char* gA0 = (const char*)(A0 + bz * sA);
    const char* gA1 = (const char*)(A1 + bz * sA);   // unused in MODE 0
    const char* gB0 = (const char*)(B0 + bz * sB);
    const char* gB1 = (const char*)(B1 + bz * sB);   // unused in MODE 1
    const size_t rowB = (size_t)Kpass * 2;

    const uint32_t sb = smem_u32(smem);
    const int ch0 = tid, ch1 = tid + 256;
    const int r0c = ch0 >> 2, c0c = (ch0 & 3) * 16;
    const int r1c = ch1 >> 2, c1c = (ch1 & 3) * 16;
    const uint32_t so0 = (uint32_t)(r0c * SROW + c0c);
    const uint32_t so1 = (uint32_t)(r1c * SROW + c1c);

    auto issue = [&](int t, int buf) {
        const size_t kb = (size_t)t * (KTILE * 2);
        const uint32_t s = sb + buf * BUFB3;
        const size_t ga0 = (size_t)(m0 + r0c) * rowB + kb + c0c;
        const size_t ga1 = (size_t)(m0 + r1c) * rowB + kb + c1c;
        const size_t gb0 = (size_t)(n0 + r0c) * rowB + kb + c0c;
        const size_t gb1 = (size_t)(n0 + r1c) * rowB + kb + c1c;
        if (MODE == 0) {
            cp16(s            + so0, gA0 + ga0);
            cp16(s            + so1, gA0 + ga1);
            cp16(s +   ABYTES + so0, gB0 + gb0);
            cp16(s +   ABYTES + so1, gB0 + gb1);
            cp16(s + 2*ABYTES + so0, gB1 + gb0);
            cp16(s + 2*ABYTES + so1, gB1 + gb1);
        } else {
            cp16(s            + so0, gA0 + ga0);
            cp16(s            + so1, gA0 + ga1);
            cp16(s +   ABYTES + so0, gA1 + ga0);
            cp16(s +   ABYTES + so1, gA1 + ga1);
            cp16(s + 2*ABYTES + so0, gB0 + gb0);
            cp16(s + 2*ABYTES + so1, gB0 + gb1);
        }
        CP_COMMIT();
    };

    float acc[4][4][4];
    #pragma unroll
    for (int i = 0; i < 4; i++)
        #pragma unroll
        for (int j = 0; j < 4; j++)
            #pragma unroll
            for (int q = 0; q < 4; q++) acc[i][j][q] = 0.f;

    const int nt = Kpass / KTILE;
    const int lr = lane & 15, lc = (lane >> 4) * 16;

    issue(0, 0);
    for (int t = 0; t < nt; t++) {
        const int buf = t & 1;
        CP_WAIT0();
        __syncthreads();
        if (t + 1 < nt) issue(t + 1, buf ^ 1);

        const uint32_t s0 = sb + buf * BUFB3;
        const uint32_t s1 = s0 + ABYTES;
        const uint32_t s2 = s0 + 2 * ABYTES;

        #pragma unroll
        for (int ks = 0; ks < 2; ks++) {
            const int kof = ks * 32;
            #pragma unroll
            for (int half = 0; half < 1; half++) {}  // no-op keeps structure flat
            if (MODE == 0) {
                uint32_t af[4][4], bh[2][4], bl[2][4];
                #pragma unroll
                for (int mt = 0; mt < 4; mt++) {
                    uint32_t off = (uint32_t)((wm * 64 + mt * 16 + lr) * SROW + kof + lc);
                    ldsm4(af[mt], s0 + off);
                }
                #pragma unroll
                for (int p = 0; p < 2; p++) {
                    uint32_t off = (uint32_t)((wn * 32 + p * 16 + lr) * SROW + kof + lc);
                    ldsm4(bh[p], s1 + off);
                    ldsm4(bl[p], s2 + off);
                }
                #pragma unroll
                for (int mt = 0; mt < 4; mt++) {
                    #pragma unroll
                    for (int ntl = 0; ntl < 4; ntl++) {
                        const int p = ntl >> 1, h = ntl & 1;
                        mma_fp16(acc[mt][ntl], af[mt], bh[p][h], bh[p][h + 2]);
                        mma_fp16(acc[mt][ntl], af[mt], bl[p][h], bl[p][h + 2]);
                    }
                }
            } else {
                uint32_t ah[4][4], al[4][4], bf_[2][4];
                #pragma unroll
                for (int mt = 0; mt < 4; mt++) {
                    uint32_t off = (uint32_t)((wm * 64 + mt * 16 + lr) * SROW + kof + lc);
                    ldsm4(ah[mt], s0 + off);
                    ldsm4(al[mt], s1 + off);
                }
                #pragma unroll
                for (int p = 0; p < 2; p++) {
                    uint32_t off = (uint32_t)((wn * 32 + p * 16 + lr) * SROW + kof + lc);
                    ldsm4(bf_[p], s2 + off);
                }
                #pragma unroll
                for (int mt = 0; mt < 4; mt++) {
                    #pragma unroll
                    for (int ntl = 0; ntl < 4; ntl++) {
                        const int p = ntl >> 1, h = ntl & 1;
                        mma_fp16(acc[mt][ntl], ah[mt], bf_[p][h], bf_[p][h + 2]);
                        mma_fp16(acc[mt][ntl], al[mt], bf_[p][h], bf_[p][h + 2]);
                    }
                }
            }
        }
        __syncthreads();
    }

    // ---- epilogue ----
    const int n_base = n0 + wn * 32;
    const int m_base = m0 + wm * 64;
    #pragma unroll
    for (int ntl = 0; ntl < 4; ntl++) {
        const int n = n_base + ntl * 8 + 2 * (lane & 3);
        #pragma unroll
        for (int mt = 0; mt < 4; mt++) {
            #pragma unroll
            for (int half = 0; half < 2; half++) {
                const int m = m_base + mt * 16 + (lane >> 2) + half * 8;
                float v0 = acc[mt][ntl][half * 2 + 0];
                float v1 = acc[mt][ntl][half * 2 + 1];
                if (EPI == 4) {
                    float bm = bias[bz * sBias + m];
                    const float* rp = resid + bz * sResid + (size_t)m * ldc + n;
                    v0 += bm + rp[0]; v1 += bm + rp[1];
                    *(float2*)(C + bz * sC + (size_t)m * ldc + n) = make_float2(v0, v1);
                } else { // EPI == 6: fp16 single
                    __half2 o; o.x = __float2half_rn(v0); o.y = __float2half_rn(v1);
                    *(__half2*)(Cf + bz * sCf + (size_t)m * ldc + n) = o;
                }
            }
        }
    }
}

// ---------------- softmax: fp32 scores row -> single fp16 A ------------------
__global__ __launch_bounds__(256) void softmax_f16(
    const float* __restrict__ S, fp16* __restrict__ Af)
{
    const float* p = S + (size_t)blockIdx.x * HW;
    fp16* a = Af + (size_t)blockIdx.x * HW;
    int tid = threadIdx.x;
    float vals[16];
    float mx = -INFINITY;
    #pragma unroll
    for (int i = 0; i < 16; i++) { vals[i] = p[tid + i * 256]; mx = fmaxf(mx, vals[i]); }
    __shared__ float sh[8];
    int w = tid >> 5, lane = tid & 31;
    mx = warpMax(mx);
    if (lane == 0) sh[w] = mx;
    __syncthreads();
    if (w == 0) {
        float v = (lane < 8) ? sh[lane] : -INFINITY;
        v = warpMax(v);
        if (lane == 0) sh[0] = v;
    }
    __syncthreads();
    mx = sh[0];
    __syncthreads();
    float s = 0.f;
    #pragma unroll
    for (int i = 0; i < 16; i++) { vals[i] = expf(vals[i] - mx); s += vals[i]; }
    s = warpSum(s);
    if (lane == 0) sh[w] = s;
    __syncthreads();
    if (w == 0) {
        float v = (lane < 8) ? sh[lane] : 0.f;
        v = warpSum(v);
        if (lane == 0) sh[0] = v;
    }
    __syncthreads();
    float invs = 1.f / sh[0];
    #pragma unroll
    for (int i = 0; i < 16; i++)
        a[tid + i * 256] = __float2half_rn(vals[i] * invs);
}

// ---------------- launch -----------------------------------------------------
extern "C" void kernel_launch(void* const* d_in, const int* in_sizes, int n_in,
                              void* d_out, int out_size)
{
    const float* x_fcc = (const float*)d_in[0];
    const float* x_fss = (const float*)d_in[1];
    const float* w1  = (const float*)d_in[2];
    const float* b1  = (const float*)d_in[3];
    const float* w2  = (const float*)d_in[4];
    const float* b2  = (const float*)d_in[5];
    const float* w3  = (const float*)d_in[6];
    const float* b3  = (const float*)d_in[7];
    const float* wrs = (const float*)d_in[8];
    const float* brs = (const float*)d_in[9];
    float* out = (float*)d_out;

    #define SYM(p, s) void* p##_; cudaGetSymbolAddress(&p##_, s); auto p = (decltype(&s[0]))p##_;
    SYM(pMcc, g_mean_cc) SYM(pIcc, g_inv_cc) SYM(pMss, g_mean_ss) SYM(pIss, g_inv_ss)
    SYM(pB1, g_b1p) SYM(pB2, g_b2p)
    SYM(pW1h, g_W1h) SYM(pW1l, g_W1l) SYM(pW2h, g_W2h) SYM(pW2l, g_W2l)
    SYM(pw3h, g_w3h) SYM(pw3l, g_w3l) SYM(pwrh, g_wrh) SYM(pwrl, g_wrl)
    SYM(pXch, g_Xch) SYM(pXcl, g_Xcl) SYM(pXsh, g_Xsh) SYM(pXsl, g_Xsl)
    SYM(pQh, g_Qh) SYM(pQl, g_Ql) SYM(pKh, g_Kh) SYM(pKl, g_Kl)
    SYM(pVfh, g_Vfh) SYM(pVfl, g_Vfl) SYM(pOf, g_Of) SYM(pAf, g_Af) SYM(pS, g_S)
    #undef SYM

    cudaFuncSetAttribute(hgemm<0>, cudaFuncAttributeMaxDynamicSharedMemorySize, SMEM4);
    cudaFuncSetAttribute(hgemm<1>, cudaFuncAttributeMaxDynamicSharedMemorySize, SMEM4);
    cudaFuncSetAttribute(hgemm<5>, cudaFuncAttributeMaxDynamicSharedMemorySize, SMEM4);
    cudaFuncSetAttribute((const void*)hgemm16<6,0>, cudaFuncAttributeMaxDynamicSharedMemorySize, SMEM3);
    cudaFuncSetAttribute((const void*)hgemm16<4,1>, cudaFuncAttributeMaxDynamicSharedMemorySize, SMEM3);

    // 1) instance-norm stats
    stats_kernel<<<BATCH * CCH, 256>>>(x_fcc, pMcc, pIcc);
    stats_kernel<<<BATCH * CCH, 256>>>(x_fss, pMss, pIss);

    // 2) fold norm into W1/W2 (bf16 hi/lo) + bias; split w3 (bf16), wrs (fp16)
    fold_kernel<<<dim3(CCH, BATCH), 128>>>(w1, b1, pMcc, pIcc, pW1h, pW1l, pB1);
    fold_kernel<<<dim3(CCH, BATCH), 128>>>(w2, b2, pMss, pIss, pW2h, pW2l, pB2);
    split_kernel_bf<<<CCH * CCH / 256, 256>>>(w3,  pw3h, pw3l, CCH * CCH);
    split_kernel_fp<<<CCH * CCH / 256, 256>>>(wrs, pwrh, pwrl, CCH * CCH);

    // 3) transpose + split inputs
    transpose_split<<<dim3(HW / 32, CCH / 32, BATCH), 256>>>(x_fcc, pXch, pXcl);
    transpose_split<<<dim3(HW / 32, CCH / 32, BATCH), 256>>>(x_fss, pXsh, pXsl);

    const size_t sX = (size_t)HW * CCH;
    const size_t sW = (size_t)CCH * CCH;
    const size_t sS = (size_t)HW * HW;
    const size_t sV = (size_t)CCH * HW;

    // 4) Q = Xcc_t W1'^T + b1'[n]   (bf16 3-term, bf16 hi/lo out)
    hgemm<1><<<dim3(CCH/128, HW/128, BATCH), 256, SMEM4>>>(
        pXch, pXcl, pW1h, pW1l, CCH, sX, sW,
        nullptr, 0, pQh, pQl, sX, CCH, pB1, CCH);
    //    K = Xss_t W2'^T + b2'[n]
    hgemm<1><<<dim3(CCH/128, HW/128, BATCH), 256, SMEM4>>>(
        pXsh, pXsl, pW2h, pW2l, CCH, sX, sW,
        nullptr, 0, pKh, pKl, sX, CCH, pB2, CCH);
    //    Vt = w3 Xss_t^T + b3[m]  -> fp16 hi/lo out (for fp16 AV gemm)
    hgemm<5><<<dim3(HW/128, CCH/128, BATCH), 256, SMEM4>>>(
        pw3h, pw3l, pXsh, pXsl, CCH, 0, sX,
        nullptr, 0, pVfh, pVfl, sV, HW, b3, 0);

    // 5) scores = Q K^T (fp32 out)
    hgemm<0><<<dim3(HW/128, HW/128, BATCH), 256, SMEM4>>>(
        pQh, pQl, pKh, pKl, CCH, sX, sX,
        pS, sS, nullptr, nullptr, 0, HW, nullptr, 0);

    // 6) softmax -> single fp16 A
    softmax_f16<<<BATCH * HW, 256>>>(pS, pAf);

    // 7) O = A Vt^T (fp16 2-term: A·Vh + A·Vl) -> O fp16 single
    hgemm16<6,0><<<dim3(CCH/128, HW/128, BATCH), 256, SMEM3>>>(
        pAf, nullptr, pVfh, pVfl, HW, sS, sV,
        nullptr, 0, pOf, sX, CCH, nullptr, 0, nullptr, 0);

    // 8) out = Wrs O^T + brs[m] + x_fcc (fp16 2-term: Wh·O + Wl·O, fp32 out)
    hgemm16<4,1><<<dim3(HW/128, CCH/128, BATCH), 256, SMEM3>>>(
        pwrh, pwrl, pOf, nullptr, CCH, 0, sX,
        out, (size_t)CCH * HW, nullptr, 0, HW, brs, 0, x_fcc, (size_t)CCH * HW);
}

// round 9
// speedup vs baseline: 1.3693x; 1.0241x over previous
#include <cuda_runtime.h>
#include <cuda_bf16.h>
#include <cuda_fp16.h>
#include <math.h>
#include <stdint.h>

#define BATCH 4
#define CCH   512
#define HW    4096

typedef __nv_bfloat16 bf16;
typedef __half fp16;

// ---------------- scratch (static __device__ — no allocation allowed) -------
__device__ float g_mean_cc[BATCH*CCH];
__device__ float g_inv_cc [BATCH*CCH];
__device__ float g_mean_ss[BATCH*CCH];
__device__ float g_inv_ss [BATCH*CCH];
__device__ float g_b1p[BATCH*CCH];
__device__ float g_b2p[BATCH*CCH];

__device__ bf16 g_W1h[BATCH*CCH*CCH], g_W1l[BATCH*CCH*CCH];
__device__ bf16 g_W2h[BATCH*CCH*CCH], g_W2l[BATCH*CCH*CCH];
__device__ fp16 g_w3h[CCH*CCH],       g_w3l[CCH*CCH];       // fp16 hi/lo
__device__ fp16 g_wrh[CCH*CCH],       g_wrl[CCH*CCH];

__device__ bf16 g_Xch[(size_t)BATCH*HW*CCH], g_Xcl[(size_t)BATCH*HW*CCH]; // x_fcc^T
__device__ bf16 g_Xsh[(size_t)BATCH*HW*CCH], g_Xsl[(size_t)BATCH*HW*CCH]; // x_fss^T
__device__ fp16 g_Xsf[(size_t)BATCH*HW*CCH];                              // x_fss^T fp16
__device__ bf16 g_Qh [(size_t)BATCH*HW*CCH], g_Ql [(size_t)BATCH*HW*CCH];
__device__ bf16 g_Kh [(size_t)BATCH*HW*CCH], g_Kl [(size_t)BATCH*HW*CCH];
__device__ fp16 g_Vfh[(size_t)BATCH*CCH*HW], g_Vfl[(size_t)BATCH*CCH*HW]; // V^T fp16 hi/lo
__device__ fp16 g_Of [(size_t)BATCH*HW*CCH];                              // O fp16
__device__ fp16 g_Af [(size_t)BATCH*HW*HW];                               // softmax(A) fp16
__device__ float g_S [(size_t)BATCH*HW*HW];                               // fp32 scores

// ---------------- small helpers ----------------------------------------------
__device__ __forceinline__ float warpSum(float v) {
    #pragma unroll
    for (int o = 16; o > 0; o >>= 1) v += __shfl_down_sync(0xffffffffu, v, o);
    return v;
}
__device__ __forceinline__ float warpMax(float v) {
    #pragma unroll
    for (int o = 16; o > 0; o >>= 1) v = fmaxf(v, __shfl_down_sync(0xffffffffu, v, o));
    return v;
}
__device__ __forceinline__ uint32_t smem_u32(const void* p) {
    uint32_t a;
    asm("{ .reg .u64 t; cvta.to.shared.u64 t, %1; cvt.u32.u64 %0, t; }" : "=r"(a) : "l"(p));
    return a;
}
__device__ __forceinline__ void split_bf16(float v, bf16 &hi, bf16 &lo) {
    hi = __float2bfloat16_rn(v);
    lo = __float2bfloat16_rn(v - __bfloat162float(hi));
}
__device__ __forceinline__ void split_fp16(float v, fp16 &hi, fp16 &lo) {
    hi = __float2half_rn(v);
    lo = __float2half_rn(v - __half2float(hi));
}

// ---------------- MMA primitives (baseline PTX, no 'a' features) -------------
__device__ __forceinline__ void ldsm4(uint32_t* r, uint32_t addr) {
    asm volatile("ldmatrix.sync.aligned.m8n8.x4.shared.b16 {%0,%1,%2,%3}, [%4];"
        : "=r"(r[0]), "=r"(r[1]), "=r"(r[2]), "=r"(r[3]) : "r"(addr));
}
__device__ __forceinline__ void mma_bf16(float* c, const uint32_t* a,
                                         uint32_t b0, uint32_t b1) {
    asm volatile(
        "mma.sync.aligned.m16n8k16.row.col.f32.bf16.bf16.f32 "
        "{%0,%1,%2,%3}, {%4,%5,%6,%7}, {%8,%9}, {%0,%1,%2,%3};"
        : "+f"(c[0]), "+f"(c[1]), "+f"(c[2]), "+f"(c[3])
        : "r"(a[0]), "r"(a[1]), "r"(a[2]), "r"(a[3]), "r"(b0), "r"(b1));
}
__device__ __forceinline__ void mma_fp16(float* c, const uint32_t* a,
                                         uint32_t b0, uint32_t b1) {
    asm volatile(
        "mma.sync.aligned.m16n8k16.row.col.f32.f16.f16.f32 "
        "{%0,%1,%2,%3}, {%4,%5,%6,%7}, {%8,%9}, {%0,%1,%2,%3};"
        : "+f"(c[0]), "+f"(c[1]), "+f"(c[2]), "+f"(c[3])
        : "r"(a[0]), "r"(a[1]), "r"(a[2]), "r"(a[3]), "r"(b0), "r"(b1));
}
__device__ __forceinline__ void cp16(uint32_t saddr, const void* g) {
    asm volatile("cp.async.cg.shared.global [%0], [%1], 16;"
                 :: "r"(saddr), "l"(g) : "memory");
}
#define CP_COMMIT() asm volatile("cp.async.commit_group;" ::: "memory")
#define CP_WAIT0()  asm volatile("cp.async.wait_group 0;" ::: "memory")

// ---------------- instance-norm stats ---------------------------------------
__global__ __launch_bounds__(256) void stats_kernel(
    const float* __restrict__ x, float* __restrict__ mean, float* __restrict__ inv)
{
    int row = blockIdx.x;
    const float* p = x + (size_t)row * HW;
    float s = 0.f, sq = 0.f;
    for (int i = threadIdx.x; i < HW; i += 256) { float v = p[i]; s += v; sq += v * v; }
    s = warpSum(s); sq = warpSum(sq);
    __shared__ float ss[8], ssq[8];
    int w = threadIdx.x >> 5, lane = threadIdx.x & 31;
    if (lane == 0) { ss[w] = s; ssq[w] = sq; }
    __syncthreads();
    if (threadIdx.x == 0) {
        float S = 0.f, SQ = 0.f;
        #pragma unroll
        for (int i = 0; i < 8; i++) { S += ss[i]; SQ += ssq[i]; }
        float m = S / (float)HW;
        float var = (SQ - (float)HW * m * m) / (float)(HW - 1);
        mean[row] = m;
        inv[row]  = rsqrtf(var + 1e-5f);
    }
}

// ---------------- fold inst-norm into conv weights, emit bf16 hi/lo ----------
__global__ __launch_bounds__(128) void fold_kernel(
    const float* __restrict__ W, const float* __restrict__ bias,
    const float* __restrict__ mean, const float* __restrict__ inv,
    bf16* __restrict__ Wh, bf16* __restrict__ Wl, float* __restrict__ bp)
{
    int o = blockIdx.x, b = blockIdx.y;
    const float* mr = mean + b * CCH;
    const float* ir = inv  + b * CCH;
    float part = 0.f;
    for (int c = threadIdx.x; c < CCH; c += 128) {
        float w  = W[o * CCH + c];
        float iv = ir[c];
        float wp = w * iv;
        bf16 hi, lo; split_bf16(wp, hi, lo);
        size_t idx = ((size_t)b * CCH + o) * CCH + c;
        Wh[idx] = hi; Wl[idx] = lo;
        part += w * mr[c] * iv;
    }
    part = warpSum(part);
    __shared__ float sp[4];
    int w = threadIdx.x >> 5, lane = threadIdx.x & 31;
    if (lane == 0) sp[w] = part;
    __syncthreads();
    if (threadIdx.x == 0) bp[b * CCH + o] = bias[o] - (sp[0] + sp[1] + sp[2] + sp[3]);
}

// ---------------- weight splits ----------------------------------------------
__global__ __launch_bounds__(256) void split_kernel_fp(
    const float* __restrict__ W, fp16* __restrict__ Wh, fp16* __restrict__ Wl, int n)
{
    int i = blockIdx.x * 256 + threadIdx.x;
    if (i < n) { fp16 hi, lo; split_fp16(W[i], hi, lo); Wh[i] = hi; Wl[i] = lo; }
}

// ---------------- transpose + split: X[C][HW] -> Xt hi/lo [HW][C] ------------
// FP16OUT: also emit single-fp16 copy
template<int FP16OUT>
__global__ __launch_bounds__(256) void transpose_split(
    const float* __restrict__ X, bf16* __restrict__ Th, bf16* __restrict__ Tl,
    fp16* __restrict__ Tf)
{
    int b = blockIdx.z;
    X  += (size_t)b * CCH * HW;
    Th += (size_t)b * HW * CCH;
    Tl += (size_t)b * HW * CCH;
    if (FP16OUT) Tf += (size_t)b * HW * CCH;
    __shared__ float t[32][33];
    int p0 = blockIdx.x * 32, c0 = blockIdx.y * 32;
    int tx = threadIdx.x & 31, ty = threadIdx.x >> 5;   // 32 x 8
    #pragma unroll
    for (int j = 0; j < 4; j++) {
        int cl = ty * 4 + j;
        t[cl][tx] = X[(size_t)(c0 + cl) * HW + p0 + tx];
    }
    __syncthreads();
    #pragma unroll
    for (int j = 0; j < 4; j++) {
        int pl = ty * 4 + j;
        float v = t[tx][pl];
        bf16 hi, lo; split_bf16(v, hi, lo);
        size_t idx = (size_t)(p0 + pl) * CCH + c0 + tx;
        Th[idx] = hi; Tl[idx] = lo;
        if (FP16OUT) Tf[idx] = __float2half_rn(v);
    }
}

// ============= bf16 3-term NT GEMM (2-stage, 80KB, single barrier/tile) ======
// EPI: 0 fp32 C; 1 bias[n] + bf16 hi/lo
#define KTILE 32
#define SROW  80
#define ABYTES (128 * SROW)          // 10240
#define BUFB4 (4 * ABYTES)           // 40960 (Ah, Al, Bh, Bl)
#define SMEM4 (2 * BUFB4)            // 81920
#define BUFB3 (3 * ABYTES)           // 30720
#define SMEM3 (2 * BUFB3)            // 61440

template<int EPI>
__global__ __launch_bounds__(256) void hgemm(
    const bf16* __restrict__ Ah, const bf16* __restrict__ Al,
    const bf16* __restrict__ Bh, const bf16* __restrict__ Bl,
    int Kpass, size_t sA, size_t sB,
    float* __restrict__ C, size_t sC,
    bf16* __restrict__ Chi, bf16* __restrict__ Clo, size_t sCh,
    int ldc,
    const float* __restrict__ bias, size_t sBias)
{
    extern __shared__ __align__(16) char smem[];
    const int tid  = threadIdx.x;
    const int wid  = tid >> 5, lane = tid & 31;
    const int wm   = wid >> 2, wn = wid & 3;
    const int bz   = blockIdx.z;
    const int m0   = blockIdx.y * 128;
    const int n0   = blockIdx.x * 128;

    const char* gAh = (const char*)(Ah + bz * sA);
    const char* gAl = (const char*)(Al + bz * sA);
    const char* gBh = (const char*)(Bh + bz * sB);
    const char* gBl = (const char*)(Bl + bz * sB);
    const size_t rowB = (size_t)Kpass * 2;

    const uint32_t sb = smem_u32(smem);
    const int ch0 = tid, ch1 = tid + 256;
    const int r0c = ch0 >> 2, c0c = (ch0 & 3) * 16;
    const int r1c = ch1 >> 2, c1c = (ch1 & 3) * 16;
    const uint32_t so0 = (uint32_t)(r0c * SROW + c0c);
    const uint32_t so1 = (uint32_t)(r1c * SROW + c1c);

    auto issue = [&](int t, int buf) {
        const size_t kb = (size_t)t * (KTILE * 2);
        const uint32_t s = sb + buf * BUFB4;
        const size_t ga0 = (size_t)(m0 + r0c) * rowB + kb + c0c;
        const size_t ga1 = (size_t)(m0 + r1c) * rowB + kb + c1c;
        const size_t gb0 = (size_t)(n0 + r0c) * rowB + kb + c0c;
        const size_t gb1 = (size_t)(n0 + r1c) * rowB + kb + c1c;
        cp16(s            + so0, gAh + ga0);
        cp16(s            + so1, gAh + ga1);
        cp16(s +   ABYTES + so0, gAl + ga0);
        cp16(s +   ABYTES + so1, gAl + ga1);
        cp16(s + 2*ABYTES + so0, gBh + gb0);
        cp16(s + 2*ABYTES + so1, gBh + gb1);
        cp16(s + 3*ABYTES + so0, gBl + gb0);
        cp16(s + 3*ABYTES + so1, gBl + gb1);
        CP_COMMIT();
    };

    float acc[4][4][4];
    #pragma unroll
    for (int i = 0; i < 4; i++)
        #pragma unroll
        for (int j = 0; j < 4; j++)
            #pragma unroll
            for (int q = 0; q < 4; q++) acc[i][j][q] = 0.f;

    const int nt = Kpass / KTILE;
    const int lr = lane & 15, lc = (lane >> 4) * 16;

    issue(0, 0);
    for (int t = 0; t < nt; t++) {
        const int buf = t & 1;
        CP_WAIT0();
        __syncthreads();      // all warps done with buf^1 (iter t-1); tile t visible
        if (t + 1 < nt) issue(t + 1, buf ^ 1);

        const uint32_t aH = sb + buf * BUFB4;
        const uint32_t aL = aH + ABYTES;
        const uint32_t bH = aH + 2 * ABYTES;
        const uint32_t bL = aH + 3 * ABYTES;

        #pragma unroll
        for (int ks = 0; ks < 2; ks++) {
            const int kof = ks * 32;
            uint32_t ah[4][4], al[4][4], bh[2][4], bl[2][4];
            #pragma unroll
            for (int mt = 0; mt < 4; mt++) {
                uint32_t off = (uint32_t)((wm * 64 + mt * 16 + lr) * SROW + kof + lc);
                ldsm4(ah[mt], aH + off);
                ldsm4(al[mt], aL + off);
            }
            #pragma unroll
            for (int p = 0; p < 2; p++) {
                uint32_t off = (uint32_t)((wn * 32 + p * 16 + lr) * SROW + kof + lc);
                ldsm4(bh[p], bH + off);
                ldsm4(bl[p], bL + off);
            }
            #pragma unroll
            for (int mt = 0; mt < 4; mt++) {
                #pragma unroll
                for (int ntl = 0; ntl < 4; ntl++) {
                    const int p = ntl >> 1, h = ntl & 1;
                    mma_bf16(acc[mt][ntl], ah[mt], bh[p][h], bh[p][h + 2]);
                    mma_bf16(acc[mt][ntl], ah[mt], bl[p][h], bl[p][h + 2]);
                    mma_bf16(acc[mt][ntl], al[mt], bh[p][h], bh[p][h + 2]);
                }
            }
        }
    }

    // ---- epilogue ----
    const int n_base = n0 + wn * 32;
    const int m_base = m0 + wm * 64;
    #pragma unroll
    for (int ntl = 0; ntl < 4; ntl++) {
        const int n = n_base + ntl * 8 + 2 * (lane & 3);
        float bn0 = 0.f, bn1 = 0.f;
        if (EPI == 1) {
            bn0 = bias[bz * sBias + n];
            bn1 = bias[bz * sBias + n + 1];
        }
        #pragma unroll
        for (int mt = 0; mt < 4; mt++) {
            #pragma unroll
            for (int half = 0; half < 2; half++) {
                const int m = m_base + mt * 16 + (lane >> 2) + half * 8;
                float v0 = acc[mt][ntl][half * 2 + 0];
                float v1 = acc[mt][ntl][half * 2 + 1];
                if (EPI == 1) {
                    v0 += bn0; v1 += bn1;
                    bf16 h0, l0, h1, l1;
                    split_bf16(v0, h0, l0); split_bf16(v1, h1, l1);
                    __nv_bfloat162 hp; hp.x = h0; hp.y = h1;
                    __nv_bfloat162 lp; lp.x = l0; lp.y = l1;
                    *(__nv_bfloat162*)(Chi + bz * sCh + (size_t)m * ldc + n) = hp;
                    *(__nv_bfloat162*)(Clo + bz * sCh + (size_t)m * ldc + n) = lp;
                } else {
                    *(float2*)(C + bz * sC + (size_t)m * ldc + n) = make_float2(v0, v1);
                }
            }
        }
    }
}

// ============= fp16 2-term NT GEMM ==========================================
// MODE 0: A single fp16, B fp16 hi/lo (terms A·Bh + A·Bl)
// MODE 1: A fp16 hi/lo, B single fp16 (terms Ah·B + Al·B)
// EPI: 4 bias[m] + resid + fp32 C; 5 bias[m] + fp16 hi/lo; 6 fp16 single
template<int EPI, int MODE>
__global__ __launch_bounds__(256) void hgemm16(
    const fp16* __restrict__ A0, const fp16* __restrict__ A1,
    const fp16* __restrict__ B0, const fp16* __restrict__ B1,
    int Kpass, size_t sA, size_t sB,
    float* __restrict__ C, size_t sC,
    fp16* __restrict__ Cf, fp16* __restrict__ Cfl, size_t sCf,
    int ldc,
    const float* __restrict__ bias, size_t sBias,
    const float* __restrict__ resid, size_t sResid)
{
    extern __shared__ __align__(16) char smem[];
    const int tid  = threadIdx.x;
    const int wid  = tid >> 5, lane = tid & 31;
    const int wm   = wid >> 2, wn = wid & 3;
    const int bz   = blockIdx.z;
    const int m0   = blockIdx.y * 128;
    const int n0   = blockIdx.x * 128;

    const char* gA0 = (const char*)(A0 + bz * sA);
    const char* gA1 = (const char*)(A1 + bz * sA);   // unused in MODE 0
    const char* gB0 = (const char*)(B0 + bz * sB);
    const char* gB1 = (const char*)(B1 + bz * sB);   // unused in MODE 1
    const size_t rowB = (size_t)Kpass * 2;

    const uint32_t sb = smem_u32(smem);
    const int ch0 = tid, ch1 = tid + 256;
    const int r0c = ch0 >> 2, c0c = (ch0 & 3) * 16;
    const int r1c = ch1 >> 2, c1c = (ch1 & 3) * 16;
    const uint32_t so0 = (uint32_t)(r0c * SROW + c0c);
    const uint32_t so1 = (uint32_t)(r1c * SROW + c1c);

    auto issue = [&](int t, int buf) {
        const size_t kb = (size_t)t * (KTILE * 2);
        const uint32_t s = sb + buf * BUFB3;
        const size_t ga0 = (size_t)(m0 + r0c) * rowB + kb + c0c;
        const size_t ga1 = (size_t)(m0 + r1c) * rowB + kb + c1c;
        const size_t gb0 = (size_t)(n0 + r0c) * rowB + kb + c0c;
        const size_t gb1 = (size_t)(n0 + r1c) * rowB + kb + c1c;
        if (MODE == 0) {
            cp16(s            + so0, gA0 + ga0);
            cp16(s            + so1, gA0 + ga1);
            cp16(s +   ABYTES + so0, gB0 + gb0);
            cp16(s +   ABYTES + so1, gB0 + gb1);
            cp16(s + 2*ABYTES + so0, gB1 + gb0);
            cp16(s + 2*ABYTES + so1, gB1 + gb1);
        } else {
            cp16(s            + so0, gA0 + ga0);
            cp16(s            + so1, gA0 + ga1);
            cp16(s +   ABYTES + so0, gA1 + ga0);
            cp16(s +   ABYTES + so1, gA1 + ga1);
            cp16(s + 2*ABYTES + so0, gB0 + gb0);
            cp16(s + 2*ABYTES + so1, gB0 + gb1);
        }
        CP_COMMIT();
    };

    float acc[4][4][4];
    #pragma unroll
    for (int i = 0; i < 4; i++)
        #pragma unroll
        for (int j = 0; j < 4; j++)
            #pragma unroll
            for (int q = 0; q < 4; q++) acc[i][j][q] = 0.f;

    const int nt = Kpass / KTILE;
    const int lr = lane & 15, lc = (lane >> 4) * 16;

    issue(0, 0);
    for (int t = 0; t < nt; t++) {
        const int buf = t & 1;
        CP_WAIT0();
        __syncthreads();      // single barrier per tile (see hgemm)
        if (t + 1 < nt) issue(t + 1, buf ^ 1);

        const uint32_t s0 = sb + buf * BUFB3;
        const uint32_t s1 = s0 + ABYTES;
        const uint32_t s2 = s0 + 2 * ABYTES;

        #pragma unroll
        for (int ks = 0; ks < 2; ks++) {
            const int kof = ks * 32;
            if (MODE == 0) {
                uint32_t af[4][4], bh[2][4], bl[2][4];
                #pragma unroll
                for (int mt = 0; mt < 4; mt++) {
                    uint32_t off = (uint32_t)((wm * 64 + mt * 16 + lr) * SROW + kof + lc);
                    ldsm4(af[mt], s0 + off);
                }
                #pragma unroll
                for (int p = 0; p < 2; p++) {
                    uint32_t off = (uint32_t)((wn * 32 + p * 16 + lr) * SROW + kof + lc);
                    ldsm4(bh[p], s1 + off);
                    ldsm4(bl[p], s2 + off);
                }
                #pragma unroll
                for (int mt = 0; mt < 4; mt++) {
                    #pragma unroll
                    for (int ntl = 0; ntl < 4; ntl++) {
                        const int p = ntl >> 1, h = ntl & 1;
                        mma_fp16(acc[mt][ntl], af[mt], bh[p][h], bh[p][h + 2]);
                        mma_fp16(acc[mt][ntl], af[mt], bl[p][h], bl[p][h + 2]);
                    }
                }
            } else {
                uint32_t ah[4][4], al[4][4], bf_[2][4];
                #pragma unroll
                for (int mt = 0; mt < 4; mt++) {
                    uint32_t off = (uint32_t)((wm * 64 + mt * 16 + lr) * SROW + kof + lc);
                    ldsm4(ah[mt], s0 + off);
                    ldsm4(al[mt], s1 + off);
                }
                #pragma unroll
                for (int p = 0; p < 2; p++) {
                    uint32_t off = (uint32_t)((wn * 32 + p * 16 + lr) * SROW + kof + lc);
                    ldsm4(bf_[p], s2 + off);
                }
                #pragma unroll
                for (int mt = 0; mt < 4; mt++) {
                    #pragma unroll
                    for (int ntl = 0; ntl < 4; ntl++) {
                        const int p = ntl >> 1, h = ntl & 1;
                        mma_fp16(acc[mt][ntl], ah[mt], bf_[p][h], bf_[p][h + 2]);
                        mma_fp16(acc[mt][ntl], al[mt], bf_[p][h], bf_[p][h + 2]);
                    }
                }
            }
        }
    }

    // ---- epilogue ----
    const int n_base = n0 + wn * 32;
    const int m_base = m0 + wm * 64;
    #pragma unroll
    for (int ntl = 0; ntl < 4; ntl++) {
        const int n = n_base + ntl * 8 + 2 * (lane & 3);
        #pragma unroll
        for (int mt = 0; mt < 4; mt++) {
            #pragma unroll
            for (int half = 0; half < 2; half++) {
                const int m = m_base + mt * 16 + (lane >> 2) + half * 8;
                float v0 = acc[mt][ntl][half * 2 + 0];
                float v1 = acc[mt][ntl][half * 2 + 1];
                if (EPI == 4) {
                    float bm = bias[bz * sBias + m];
                    const float* rp = resid + bz * sResid + (size_t)m * ldc + n;
                    v0 += bm + rp[0]; v1 += bm + rp[1];
                    *(float2*)(C + bz * sC + (size_t)m * ldc + n) = make_float2(v0, v1);
                } else if (EPI == 5) {
                    float bm = bias[bz * sBias + m];
                    v0 += bm; v1 += bm;
                    fp16 h0, l0, h1, l1;
                    split_fp16(v0, h0, l0); split_fp16(v1, h1, l1);
                    __half2 hp; hp.x = h0; hp.y = h1;
                    __half2 lp; lp.x = l0; lp.y = l1;
                    *(__half2*)(Cf  + bz * sCf + (size_t)m * ldc + n) = hp;
                    *(__half2*)(Cfl + bz * sCf + (size_t)m * ldc + n) = lp;
                } else { // EPI == 6: fp16 single
                    __half2 o; o.x = __float2half_rn(v0); o.y = __float2half_rn(v1);
                    *(__half2*)(Cf + bz * sCf + (size_t)m * ldc + n) = o;
                }
            }
        }
    }
}

// ---------------- softmax: fp32 scores row -> single fp16 A ------------------
__global__ __launch_bounds__(256) void softmax_f16(
    const float* __restrict__ S, fp16* __restrict__ Af)
{
    const float* p = S + (size_t)blockIdx.x * HW;
    fp16* a = Af + (size_t)blockIdx.x * HW;
    int tid = threadIdx.x;
    float vals[16];
    float mx = -INFINITY;
    #pragma unroll
    for (int i = 0; i < 16; i++) { vals[i] = p[tid + i * 256]; mx = fmaxf(mx, vals[i]); }
    __shared__ float sh[8];
    int w = tid >> 5, lane = tid & 31;
    mx = warpMax(mx);
    if (lane == 0) sh[w] = mx;
    __syncthreads();
    if (w == 0) {
        float v = (lane < 8) ? sh[lane] : -INFINITY;
        v = warpMax(v);
        if (lane == 0) sh[0] = v;
    }
    __syncthreads();
    mx = sh[0];
    __syncthreads();
    float s = 0.f;
    #pragma unroll
    for (int i = 0; i < 16; i++) { vals[i] = expf(vals[i] - mx); s += vals[i]; }
    s = warpSum(s);
    if (lane == 0) sh[w] = s;
    __syncthreads();
    if (w == 0) {
        float v = (lane < 8) ? sh[lane] : 0.f;
        v = warpSum(v);
        if (lane == 0) sh[0] = v;
    }
    __syncthreads();
    float invs = 1.f / sh[0];
    #pragma unroll
    for (int i = 0; i < 16; i++)
        a[tid + i * 256] = __float2half_rn(vals[i] * invs);
}

// ---------------- launch -----------------------------------------------------
extern "C" void kernel_launch(void* const* d_in, const int* in_sizes, int n_in,
                              void* d_out, int out_size)
{
    const float* x_fcc = (const float*)d_in[0];
    const float* x_fss = (const float*)d_in[1];
    const float* w1  = (const float*)d_in[2];
    const float* b1  = (const float*)d_in[3];
    const float* w2  = (const float*)d_in[4];
    const float* b2  = (const float*)d_in[5];
    const float* w3  = (const float*)d_in[6];
    const float* b3  = (const float*)d_in[7];
    const float* wrs = (const float*)d_in[8];
    const float* brs = (const float*)d_in[9];
    float* out = (float*)d_out;

    #define SYM(p, s) void* p##_; cudaGetSymbolAddress(&p##_, s); auto p = (decltype(&s[0]))p##_;
    SYM(pMcc, g_mean_cc) SYM(pIcc, g_inv_cc) SYM(pMss, g_mean_ss) SYM(pIss, g_inv_ss)
    SYM(pB1, g_b1p) SYM(pB2, g_b2p)
    SYM(pW1h, g_W1h) SYM(pW1l, g_W1l) SYM(pW2h, g_W2h) SYM(pW2l, g_W2l)
    SYM(pw3h, g_w3h) SYM(pw3l, g_w3l) SYM(pwrh, g_wrh) SYM(pwrl, g_wrl)
    SYM(pXch, g_Xch) SYM(pXcl, g_Xcl) SYM(pXsh, g_Xsh) SYM(pXsl, g_Xsl) SYM(pXsf, g_Xsf)
    SYM(pQh, g_Qh) SYM(pQl, g_Ql) SYM(pKh, g_Kh) SYM(pKl, g_Kl)
    SYM(pVfh, g_Vfh) SYM(pVfl, g_Vfl) SYM(pOf, g_Of) SYM(pAf, g_Af) SYM(pS, g_S)
    #undef SYM

    cudaFuncSetAttribute(hgemm<0>, cudaFuncAttributeMaxDynamicSharedMemorySize, SMEM4);
    cudaFuncSetAttribute(hgemm<1>, cudaFuncAttributeMaxDynamicSharedMemorySize, SMEM4);
    cudaFuncSetAttribute((const void*)hgemm16<6,0>, cudaFuncAttributeMaxDynamicSharedMemorySize, SMEM3);
    cudaFuncSetAttribute((const void*)hgemm16<5,1>, cudaFuncAttributeMaxDynamicSharedMemorySize, SMEM3);
    cudaFuncSetAttribute((const void*)hgemm16<4,1>, cudaFuncAttributeMaxDynamicSharedMemorySize, SMEM3);

    // 1) instance-norm stats
    stats_kernel<<<BATCH * CCH, 256>>>(x_fcc, pMcc, pIcc);
    stats_kernel<<<BATCH * CCH, 256>>>(x_fss, pMss, pIss);

    // 2) fold norm into W1/W2 (bf16 hi/lo) + bias; split w3 (fp16), wrs (fp16)
    fold_kernel<<<dim3(CCH, BATCH), 128>>>(w1, b1, pMcc, pIcc, pW1h, pW1l, pB1);
    fold_kernel<<<dim3(CCH, BATCH), 128>>>(w2, b2, pMss, pIss, pW2h, pW2l, pB2);
    split_kernel_fp<<<CCH * CCH / 256, 256>>>(w3,  pw3h, pw3l, CCH * CCH);
    split_kernel_fp<<<CCH * CCH / 256, 256>>>(wrs, pwrh, pwrl, CCH * CCH);

    // 3) transpose + split inputs (x_fss also as single fp16 for the V gemm)
    transpose_split<0><<<dim3(HW / 32, CCH / 32, BATCH), 256>>>(x_fcc, pXch, pXcl, nullptr);
    transpose_split<1><<<dim3(HW / 32, CCH / 32, BATCH), 256>>>(x_fss, pXsh, pXsl, pXsf);

    const size_t sX = (size_t)HW * CCH;
    const size_t sW = (size_t)CCH * CCH;
    const size_t sS = (size_t)HW * HW;
    const size_t sV = (size_t)CCH * HW;

    // 4) Q = Xcc_t W1'^T + b1'[n]   (bf16 3-term, bf16 hi/lo out)
    hgemm<1><<<dim3(CCH/128, HW/128, BATCH), 256, SMEM4>>>(
        pXch, pXcl, pW1h, pW1l, CCH, sX, sW,
        nullptr, 0, pQh, pQl, sX, CCH, pB1, CCH);
    //    K = Xss_t W2'^T + b2'[n]
    hgemm<1><<<dim3(CCH/128, HW/128, BATCH), 256, SMEM4>>>(
        pXsh, pXsl, pW2h, pW2l, CCH, sX, sW,
        nullptr, 0, pKh, pKl, sX, CCH, pB2, CCH);
    //    Vt = w3 Xss_t^T + b3[m] (fp16 2-term: w3h·X + w3l·X) -> fp16 hi/lo out
    hgemm16<5,1><<<dim3(HW/128, CCH/128, BATCH), 256, SMEM3>>>(
        pw3h, pw3l, pXsf, nullptr, CCH, 0, sX,
        nullptr, 0, pVfh, pVfl, sV, HW, b3, 0, nullptr, 0);

    // 5) scores = Q K^T (bf16 3-term, fp32 out)
    hgemm<0><<<dim3(HW/128, HW/128, BATCH), 256, SMEM4>>>(
        pQh, pQl, pKh, pKl, CCH, sX, sX,
        pS, sS, nullptr, nullptr, 0, HW, nullptr, 0);

    // 6) softmax -> single fp16 A
    softmax_f16<<<BATCH * HW, 256>>>(pS, pAf);

    // 7) O = A Vt^T (fp16 2-term: A·Vh + A·Vl) -> O fp16 single
    hgemm16<6,0><<<dim3(CCH/128, HW/128, BATCH), 256, SMEM3>>>(
        pAf, nullptr, pVfh, pVfl, HW, sS, sV,
        nullptr, 0, pOf, nullptr, sX, CCH, nullptr, 0, nullptr, 0);

    // 8) out = Wrs O^T + brs[m] + x_fcc (fp16 2-term: Wh·O + Wl·O, fp32 out)
    hgemm16<4,1><<<dim3(HW/128, CCH/128, BATCH), 256, SMEM3>>>(
        pwrh, pwrl, pOf, nullptr, CCH, 0, sX,
        out, (size_t)CCH * HW, nullptr, nullptr, 0, HW, brs, 0, x_fcc, (size_t)CCH * HW);
}